// round 2
// baseline (speedup 1.0000x reference)
#include <cuda_runtime.h>
#include <cuda_bf16.h>
#include <stdint.h>

#define KNS 100000
#define KNT 50000
#define KE  600000
#define KD  128
#define BN_EPS 1e-5f
#define SROW 136   // smem row stride in bf16 elems (128 + 8 pad -> conflict-free)

// ---------------- scratch (static device memory; no allocations) ----------------
__device__ float g_h[KNT * KD];        // aggregated features
__device__ float g_y1[KNT * KD];       // layer-1 pre-BN output
__device__ int   g_counts[KNT];
__device__ int   g_offsets[KNT + 1];
__device__ int   g_cursor[KNT];
__device__ int   g_srcs[KE];
__device__ float g_partial[200 * 256]; // per-block [sum(128) | sq(128)] partials
__device__ float g_stats[2 * KD];      // [sum | sq] for current layer
__device__ float g_scale[2 * KD];
__device__ float g_shift[2 * KD];
__device__ int   g_bsum[128];

// ---------------- init ----------------
__global__ void zero_kernel() {
  int i = blockIdx.x * blockDim.x + threadIdx.x;
  if (i < KNT) g_counts[i] = 0;
}

// ---------------- CSR build (indices are int32: JAX default x64-disabled) --------
__global__ void hist_kernel(const int* __restrict__ dst) {
  int i = blockIdx.x * blockDim.x + threadIdx.x;
  if (i < KE) atomicAdd(&g_counts[dst[i]], 1);
}

__device__ __forceinline__ int warp_incl_scan(int x, int lane) {
#pragma unroll
  for (int o = 1; o < 32; o <<= 1) {
    int y = __shfl_up_sync(0xffffffffu, x, o);
    if (lane >= o) x += y;
  }
  return x;
}

__global__ void scan1_kernel() {
  int t = threadIdx.x, b = blockIdx.x;
  int i = b * 512 + t;
  int v = (i < KNT) ? g_counts[i] : 0;
  int lane = t & 31, w = t >> 5;
  int x = warp_incl_scan(v, lane);
  __shared__ int ws[16];
  if (lane == 31) ws[w] = x;
  __syncthreads();
  if (t < 16) {
    int y = ws[t];
#pragma unroll
    for (int o = 1; o < 16; o <<= 1) {
      int z = __shfl_up_sync(0xffffu, y, o);
      if (t >= o) y += z;
    }
    ws[t] = y;
  }
  __syncthreads();
  int incl = x + (w > 0 ? ws[w - 1] : 0);
  if (i < KNT) g_offsets[i] = incl - v;  // block-local exclusive
  if (t == 511) g_bsum[b] = incl;        // block total
}

__global__ void scan2_kernel() {
  int t = threadIdx.x;  // 128 threads, 98 valid
  int v = (t < 98) ? g_bsum[t] : 0;
  int lane = t & 31, w = t >> 5;
  int x = warp_incl_scan(v, lane);
  __shared__ int ws[4];
  if (lane == 31) ws[w] = x;
  __syncthreads();
  if (t < 4) {
    int y = ws[t];
#pragma unroll
    for (int o = 1; o < 4; o <<= 1) {
      int z = __shfl_up_sync(0xfu, y, o);
      if (t >= o) y += z;
    }
    ws[t] = y;
  }
  __syncthreads();
  int incl = x + (w > 0 ? ws[w - 1] : 0);
  if (t < 98) g_bsum[t] = incl - v;      // exclusive block bases
  if (t == 127) g_offsets[KNT] = incl;   // grand total (= KE)
}

__global__ void scan3_kernel() {
  int t = threadIdx.x, b = blockIdx.x;
  int i = b * 512 + t;
  if (i < KNT) {
    int o = g_offsets[i] + g_bsum[b];
    g_offsets[i] = o;
    g_cursor[i] = o;
  }
}

__global__ void scatter_kernel(const int* __restrict__ src,
                               const int* __restrict__ dst) {
  int i = blockIdx.x * blockDim.x + threadIdx.x;
  if (i < KE) {
    int d = dst[i];
    int p = atomicAdd(&g_cursor[d], 1);
    g_srcs[p] = src[i];
  }
}

// ---------------- aggregation: one warp per target, no float atomics ----------------
__global__ void aggregate_kernel(const float* __restrict__ xs,
                                 const float* __restrict__ xt,
                                 const float* __restrict__ eps) {
  int gw = (blockIdx.x * blockDim.x + threadIdx.x) >> 5;
  int lane = threadIdx.x & 31;
  if (gw >= KNT) return;
  float sc = 1.0f + eps[0];
  const float4* xt4 = reinterpret_cast<const float4*>(xt) + (size_t)gw * 32;
  float4 a = xt4[lane];
  a.x *= sc; a.y *= sc; a.z *= sc; a.w *= sc;
  float4 b = make_float4(0.f, 0.f, 0.f, 0.f);
  int beg = g_offsets[gw], end = g_offsets[gw + 1];
  const float4* xs4 = reinterpret_cast<const float4*>(xs);
  int i = beg;
  for (; i + 1 < end; i += 2) {
    int s0 = g_srcs[i], s1 = g_srcs[i + 1];
    float4 v0 = xs4[(size_t)s0 * 32 + lane];
    float4 v1 = xs4[(size_t)s1 * 32 + lane];
    a.x += v0.x; a.y += v0.y; a.z += v0.z; a.w += v0.w;
    b.x += v1.x; b.y += v1.y; b.z += v1.z; b.w += v1.w;
  }
  if (i < end) {
    int s0 = g_srcs[i];
    float4 v0 = xs4[(size_t)s0 * 32 + lane];
    a.x += v0.x; a.y += v0.y; a.z += v0.z; a.w += v0.w;
  }
  a.x += b.x; a.y += b.y; a.z += b.z; a.w += b.w;
  reinterpret_cast<float4*>(g_h)[(size_t)gw * 32 + lane] = a;
}

// ---------------- GEMM: bf16 split (hi/lo) tensor-core, fp32-quality ----------------
__device__ __forceinline__ void mma_bf16(float* c, const uint32_t* a,
                                         uint32_t b0, uint32_t b1) {
  asm volatile(
      "mma.sync.aligned.m16n8k16.row.col.f32.bf16.bf16.f32 "
      "{%0,%1,%2,%3}, {%4,%5,%6,%7}, {%8,%9}, {%0,%1,%2,%3};\n"
      : "+f"(c[0]), "+f"(c[1]), "+f"(c[2]), "+f"(c[3])
      : "r"(a[0]), "r"(a[1]), "r"(a[2]), "r"(a[3]), "r"(b0), "r"(b1));
}

__device__ __forceinline__ void split_bf16(float x, __nv_bfloat16& h, __nv_bfloat16& l) {
  h = __float2bfloat16_rn(x);
  l = __float2bfloat16_rn(x - __bfloat162float(h));
}

// LAYER==1: A = g_h,                out = g_y1
// LAYER==2: A = relu(bn1(g_y1)),    out = param (d_out)
template <int LAYER>
__global__ __launch_bounds__(256) void gemm_kernel(const float* __restrict__ W,
                                                   const float* __restrict__ bias,
                                                   float* __restrict__ out_param) {
  extern __shared__ __nv_bfloat16 sm[];
  __nv_bfloat16* Ah = sm;
  __nv_bfloat16* Al = Ah + 64 * SROW;
  __nv_bfloat16* Wh = Al + 64 * SROW;
  __nv_bfloat16* Wl = Wh + 128 * SROW;
  float* biasS = reinterpret_cast<float*>(Wl + 128 * SROW);

  const float* A = (LAYER == 1) ? g_h : g_y1;
  float* out = (LAYER == 1) ? g_y1 : out_param;

  int t = threadIdx.x;
  int row0 = blockIdx.x * 64;

  if (t < 128) biasS[t] = bias[t];

  // stage W (128x128) as hi/lo bf16
  for (int idx = t; idx < 128 * 32; idx += 256) {
    int r = idx >> 5;
    int c = (idx & 31) << 2;
    float4 v = *reinterpret_cast<const float4*>(W + r * 128 + c);
    float vv[4] = {v.x, v.y, v.z, v.w};
#pragma unroll
    for (int j = 0; j < 4; j++) {
      __nv_bfloat16 h, l;
      split_bf16(vv[j], h, l);
      Wh[r * SROW + c + j] = h;
      Wl[r * SROW + c + j] = l;
    }
  }
  // stage A (64x128) as hi/lo bf16 (layer-2: fused BN1 + ReLU)
  for (int idx = t; idx < 64 * 32; idx += 256) {
    int r = idx >> 5;
    int c = (idx & 31) << 2;
    int grow = row0 + r;
    float4 v = make_float4(0.f, 0.f, 0.f, 0.f);
    if (grow < KNT) v = *reinterpret_cast<const float4*>(A + (size_t)grow * 128 + c);
    float vv[4] = {v.x, v.y, v.z, v.w};
#pragma unroll
    for (int j = 0; j < 4; j++) {
      float x = vv[j];
      if (LAYER == 2)
        x = fmaxf(fmaf(__ldg(&g_scale[c + j]), x, __ldg(&g_shift[c + j])), 0.f);
      __nv_bfloat16 h, l;
      split_bf16(x, h, l);
      Ah[r * SROW + c + j] = h;
      Al[r * SROW + c + j] = l;
    }
  }
  __syncthreads();

  int w = t >> 5, lane = t & 31;
  int rq = lane >> 2;         // 0..7
  int kq = (lane & 3) << 1;   // 0,2,4,6
  int rb = (w >> 1) * 16;     // warp row base in tile
  int cb = (w & 1) * 64;      // warp col base

  float acc[8][4];
#pragma unroll
  for (int i = 0; i < 8; i++)
#pragma unroll
    for (int j = 0; j < 4; j++) acc[i][j] = 0.f;

#pragma unroll
  for (int kk = 0; kk < 128; kk += 16) {
    uint32_t ah[4], al[4];
    const __nv_bfloat16* pa = &Ah[(rb + rq) * SROW + kk + kq];
    const __nv_bfloat16* pl = &Al[(rb + rq) * SROW + kk + kq];
    ah[0] = *reinterpret_cast<const uint32_t*>(pa);
    ah[1] = *reinterpret_cast<const uint32_t*>(pa + 8 * SROW);
    ah[2] = *reinterpret_cast<const uint32_t*>(pa + 8);
    ah[3] = *reinterpret_cast<const uint32_t*>(pa + 8 * SROW + 8);
    al[0] = *reinterpret_cast<const uint32_t*>(pl);
    al[1] = *reinterpret_cast<const uint32_t*>(pl + 8 * SROW);
    al[2] = *reinterpret_cast<const uint32_t*>(pl + 8);
    al[3] = *reinterpret_cast<const uint32_t*>(pl + 8 * SROW + 8);
#pragma unroll
    for (int nt = 0; nt < 8; nt++) {
      const __nv_bfloat16* pb  = &Wh[(cb + nt * 8 + rq) * SROW + kk + kq];
      const __nv_bfloat16* pbl = &Wl[(cb + nt * 8 + rq) * SROW + kk + kq];
      uint32_t bh0 = *reinterpret_cast<const uint32_t*>(pb);
      uint32_t bh1 = *reinterpret_cast<const uint32_t*>(pb + 8);
      uint32_t bl0 = *reinterpret_cast<const uint32_t*>(pbl);
      uint32_t bl1 = *reinterpret_cast<const uint32_t*>(pbl + 8);
      mma_bf16(acc[nt], ah, bh0, bh1);  // hi*hi
      mma_bf16(acc[nt], al, bh0, bh1);  // lo*hi
      mma_bf16(acc[nt], ah, bl0, bl1);  // hi*lo
    }
  }

#pragma unroll
  for (int nt = 0; nt < 8; nt++) {
    int col = cb + nt * 8 + kq;
    float b0 = biasS[col], b1v = biasS[col + 1];
    int r = row0 + rb + rq;
    if (r < KNT) {
      float2 o = make_float2(acc[nt][0] + b0, acc[nt][1] + b1v);
      *reinterpret_cast<float2*>(out + (size_t)r * 128 + col) = o;
    }
    if (r + 8 < KNT) {
      float2 o = make_float2(acc[nt][2] + b0, acc[nt][3] + b1v);
      *reinterpret_cast<float2*>(out + (size_t)(r + 8) * 128 + col) = o;
    }
  }
}

// ---------------- BN statistics (deterministic two-stage reduction) ----------------
__global__ void colstats_kernel(const float* __restrict__ y_param, int which) {
  const float* y = (which == 0) ? g_y1 : y_param;
  int t = threadIdx.x;  // 128: one column each
  int b = blockIdx.x;   // 200 blocks * 250 rows
  int r0 = b * 250, r1 = r0 + 250;
  float s = 0.f, q = 0.f;
  for (int r = r0; r < r1; r++) {
    float v = y[(size_t)r * 128 + t];
    s += v;
    q = fmaf(v, v, q);
  }
  g_partial[b * 256 + t] = s;
  g_partial[b * 256 + 128 + t] = q;
}

__global__ void statsreduce_kernel() {
  int t = threadIdx.x;  // 256: sums then squares
  float acc = 0.f;
  for (int b = 0; b < 200; b++) acc += g_partial[b * 256 + t];
  g_stats[t] = acc;
}

__global__ void params_kernel(const float* __restrict__ gamma,
                              const float* __restrict__ beta, int which) {
  int t = threadIdx.x;  // 128
  float inv = 1.0f / (float)KNT;
  float mu = g_stats[t] * inv;
  float var = g_stats[128 + t] * inv - mu * mu;
  float r = rsqrtf(var + BN_EPS);
  float sc = gamma[t] * r;
  g_scale[which * 128 + t] = sc;
  g_shift[which * 128 + t] = beta[t] - mu * sc;
}

__global__ void finalize_kernel(float* __restrict__ out) {
  int i = blockIdx.x * blockDim.x + threadIdx.x;
  if (i >= KNT * 32) return;
  int c = (i & 31) << 2;
  float4 v = reinterpret_cast<float4*>(out)[i];
  v.x = fmaxf(fmaf(g_scale[128 + c + 0], v.x, g_shift[128 + c + 0]), 0.f);
  v.y = fmaxf(fmaf(g_scale[128 + c + 1], v.y, g_shift[128 + c + 1]), 0.f);
  v.z = fmaxf(fmaf(g_scale[128 + c + 2], v.z, g_shift[128 + c + 2]), 0.f);
  v.w = fmaxf(fmaf(g_scale[128 + c + 3], v.w, g_shift[128 + c + 3]), 0.f);
  reinterpret_cast<float4*>(out)[i] = v;
}

// ---------------- launch ----------------
extern "C" void kernel_launch(void* const* d_in, const int* in_sizes, int n_in,
                              void* d_out, int out_size) {
  const float* x_s = (const float*)d_in[0];
  const float* x_t = (const float*)d_in[1];
  const int* src = (const int*)d_in[2];   // JAX x64-disabled: int32
  const int* dst = (const int*)d_in[3];
  const float* eps = (const float*)d_in[4];
  const float* W1 = (const float*)d_in[5];
  const float* b1 = (const float*)d_in[6];
  const float* g1 = (const float*)d_in[7];
  const float* be1 = (const float*)d_in[8];
  const float* W2 = (const float*)d_in[9];
  const float* b2 = (const float*)d_in[10];
  const float* g2 = (const float*)d_in[11];
  const float* be2 = (const float*)d_in[12];
  float* out = (float*)d_out;

  const int SMEM = (64 * SROW * 2 + 128 * SROW * 2) * 2 + 128 * 4;  // 104960 B
  cudaFuncSetAttribute(gemm_kernel<1>, cudaFuncAttributeMaxDynamicSharedMemorySize, SMEM);
  cudaFuncSetAttribute(gemm_kernel<2>, cudaFuncAttributeMaxDynamicSharedMemorySize, SMEM);

  zero_kernel<<<(KNT + 255) / 256, 256>>>();
  hist_kernel<<<(KE + 255) / 256, 256>>>(dst);
  scan1_kernel<<<98, 512>>>();
  scan2_kernel<<<1, 128>>>();
  scan3_kernel<<<98, 512>>>();
  scatter_kernel<<<(KE + 255) / 256, 256>>>(src, dst);
  aggregate_kernel<<<(KNT * 32 + 255) / 256, 256>>>(x_s, x_t, eps);
  gemm_kernel<1><<<(KNT + 63) / 64, 256, SMEM>>>(W1, b1, nullptr);
  colstats_kernel<<<200, 128>>>(nullptr, 0);
  statsreduce_kernel<<<1, 256>>>();
  params_kernel<<<1, 128>>>(g1, be1, 0);
  gemm_kernel<2><<<(KNT + 63) / 64, 256, SMEM>>>(W2, b2, out);
  colstats_kernel<<<200, 128>>>(out, 1);
  statsreduce_kernel<<<1, 256>>>();
  params_kernel<<<1, 128>>>(g2, be2, 1);
  finalize_kernel<<<(KNT * 32 + 255) / 256, 256>>>(out);
}